// round 15
// baseline (speedup 1.0000x reference)
#include <cuda_runtime.h>
#include <cuda_bf16.h>
#include <cstdint>

#define D 128
#define MAX_DST 65536

// ---- scratch (__device__ globals per allocation rules) ----
__device__ __align__(16) uint32_t g_hn_hi[(size_t)MAX_DST * 64];  // 16 MB: bf16x2 hi
__device__ __align__(16) uint32_t g_hn_lo[(size_t)MAX_DST * 64];  // 16 MB: bf16x2 lo
__device__ __align__(16) __nv_bfloat16 g_Wt_hi[2 * 128 * 128];    // [src][n][k] hi
__device__ __align__(16) __nv_bfloat16 g_Wt_lo[2 * 128 * 128];    // [src][n][k] lo
__device__ float g_bsum[128];

__device__ __forceinline__ uint32_t pack_bf16_hi(float a, float b, uint32_t& lo_out) {
    __nv_bfloat16 ha = __float2bfloat16(a);
    __nv_bfloat16 hb = __float2bfloat16(b);
    __nv_bfloat16 la = __float2bfloat16(a - __bfloat162float(ha));
    __nv_bfloat16 lb = __float2bfloat16(b - __bfloat162float(hb));
    lo_out = (uint32_t)__bfloat16_as_ushort(la) | ((uint32_t)__bfloat16_as_ushort(lb) << 16);
    return (uint32_t)__bfloat16_as_ushort(ha) | ((uint32_t)__bfloat16_as_ushort(hb) << 16);
}

// ============================================================
// Kernel 1: segment-mean aggregation (one warp per dst row) with
// per-warp binary search over sorted dst (replaces the offsets pass),
// + trailing W-prep blocks (bf16 split/transpose of W, bias sum).
// Gather loop identical to the 84.1us R11 kernel.
// ============================================================
__global__ void aggregate_kernel(const float* __restrict__ feat,
                                 const int* __restrict__ src,
                                 const int* __restrict__ dst,
                                 const float* __restrict__ Wself,
                                 const float* __restrict__ Wneigh,
                                 const float* __restrict__ bself,
                                 const float* __restrict__ bneigh,
                                 int n_edges, int n_dst, int n_agg_blocks) {
    if ((int)blockIdx.x >= n_agg_blocks) {
        // ---- W prep role ----
        int t = (blockIdx.x - n_agg_blocks) * blockDim.x + threadIdx.x;  // 0..4095
        for (int o = t; o < 2 * 128 * 128; o += 16 * 256) {
            int s = o >> 14, rem = o & 16383;
            int n = rem >> 7, k = rem & 127;
            const float* W = s ? Wneigh : Wself;
            float x = W[k * 128 + n];
            __nv_bfloat16 h = __float2bfloat16(x);
            g_Wt_hi[o] = h;
            g_Wt_lo[o] = __float2bfloat16(x - __bfloat162float(h));
        }
        if ((int)blockIdx.x == n_agg_blocks && threadIdx.x < 128)
            g_bsum[threadIdx.x] = bself[threadIdx.x] + bneigh[threadIdx.x];
        return;
    }

    int row  = (int)((blockIdx.x * blockDim.x + threadIdx.x) >> 5);
    int lane = threadIdx.x & 31;
    if (row >= n_dst) return;

    // ---- row bounds via lower_bound on sorted dst (lanes 0,1) ----
    int b = 0;
    if (lane < 2) {
        int v = row + lane;
        int sl = 0, sh = n_edges;
        while (sl < sh) {
            int m = (sl + sh) >> 1;
            if (__ldg(dst + m) < v) sl = m + 1; else sh = m;
        }
        b = sl;
    }
    int lo = __shfl_sync(0xffffffffu, b, 0);
    int hi = __shfl_sync(0xffffffffu, b, 1);

    const float4* __restrict__ fbase = (const float4*)feat;
    float ax = 0.f, ay = 0.f, az = 0.f, aw = 0.f;

    int e = lo;
    for (; e + 4 <= hi; e += 4) {
        int s0 = __ldg(src + e + 0);
        int s1 = __ldg(src + e + 1);
        int s2 = __ldg(src + e + 2);
        int s3 = __ldg(src + e + 3);
        float4 v0 = fbase[(size_t)s0 * 32 + lane];
        float4 v1 = fbase[(size_t)s1 * 32 + lane];
        float4 v2 = fbase[(size_t)s2 * 32 + lane];
        float4 v3 = fbase[(size_t)s3 * 32 + lane];
        ax += (v0.x + v1.x) + (v2.x + v3.x);
        ay += (v0.y + v1.y) + (v2.y + v3.y);
        az += (v0.z + v1.z) + (v2.z + v3.z);
        aw += (v0.w + v1.w) + (v2.w + v3.w);
    }
    for (; e < hi; ++e) {
        float4 v = fbase[(size_t)__ldg(src + e) * 32 + lane];
        ax += v.x; ay += v.y; az += v.z; aw += v.w;
    }

    float invd = 1.0f / fmaxf((float)(hi - lo), 1.0f);
    ax *= invd; ay *= invd; az *= invd; aw *= invd;

    uint32_t l0, l1;
    uint32_t h0 = pack_bf16_hi(ax, ay, l0);
    uint32_t h1 = pack_bf16_hi(az, aw, l1);
    size_t base = (size_t)row * 64 + lane * 2;
    *(uint2*)&g_hn_hi[base] = make_uint2(h0, h1);
    *(uint2*)&g_hn_lo[base] = make_uint2(l0, l1);
}

// ============================================================
// Kernel 2: double-buffered, cp.async-pipelined HMMA bf16-split GEMM
//   out = [feat[:n_dst] | hn] @ [W_self ; W_neigh] + bias
//   (byte-identical to the 84.1us R11 kernel)
// ============================================================
#define AST2 80                      // smem row stride in bytes
#define AHI 0
#define ALO 10240
#define WHI 20480
#define WLO 30720
#define STG_BYTES 40960
#define S_TOTAL (512 + 2 * STG_BYTES)   // 82432 B dynamic smem

__device__ __forceinline__ void cpa16(void* sdst, const void* gsrc) {
    uint32_t d = (uint32_t)__cvta_generic_to_shared(sdst);
    asm volatile("cp.async.cg.shared.global [%0], [%1], 16;" :: "r"(d), "l"(gsrc));
}

__device__ __forceinline__ void stage_w(char* stg, int s, int kbase, int tid) {
#pragma unroll
    for (int i = 0; i < 2; ++i) {
        int c = tid + i * 256;
        int n = c >> 2, kc = c & 3;
        size_t go = ((size_t)(s * 128 + n)) * 128 + kbase + kc * 8;
        uint32_t off = n * AST2 + kc * 16;
        cpa16(stg + WHI + off, g_Wt_hi + go);
        cpa16(stg + WLO + off, g_Wt_lo + go);
    }
}
__device__ __forceinline__ void stage_a_neigh(char* stg, int rowBase, int kbase, int tid) {
#pragma unroll
    for (int i = 0; i < 2; ++i) {
        int c = tid + i * 256;
        int r = c >> 2, kc = c & 3;
        size_t gi = (size_t)(rowBase + r) * 64 + (kbase >> 1) + kc * 4;
        uint32_t off = r * AST2 + kc * 16;
        cpa16(stg + AHI + off, g_hn_hi + gi);
        cpa16(stg + ALO + off, g_hn_lo + gi);
    }
}
__device__ __forceinline__ void lda_self(const float* feat, int rowBase, int kbase,
                                         int tid, float4* pf) {
#pragma unroll
    for (int i = 0; i < 2; ++i) {
        int c = tid + i * 256;
        int r = c >> 2, kc = c & 3;
        const float4* p = (const float4*)(feat + (size_t)(rowBase + r) * D + kbase + kc * 8);
        pf[i * 2 + 0] = p[0];
        pf[i * 2 + 1] = p[1];
    }
}
__device__ __forceinline__ void sts_self(char* stg, int tid, const float4* pf) {
#pragma unroll
    for (int i = 0; i < 2; ++i) {
        int c = tid + i * 256;
        int r = c >> 2, kc = c & 3;
        float4 x0 = pf[i * 2 + 0], x1 = pf[i * 2 + 1];
        uint32_t h0, h1, h2, h3, l0, l1, l2, l3;
        h0 = pack_bf16_hi(x0.x, x0.y, l0);
        h1 = pack_bf16_hi(x0.z, x0.w, l1);
        h2 = pack_bf16_hi(x1.x, x1.y, l2);
        h3 = pack_bf16_hi(x1.z, x1.w, l3);
        uint32_t off = r * AST2 + kc * 16;
        *(uint4*)(stg + AHI + off) = make_uint4(h0, h1, h2, h3);
        *(uint4*)(stg + ALO + off) = make_uint4(l0, l1, l2, l3);
    }
}

__device__ __forceinline__ void mma16816(float* c, const uint32_t* a, const uint32_t* b) {
    asm volatile(
        "mma.sync.aligned.m16n8k16.row.col.f32.bf16.bf16.f32 "
        "{%0,%1,%2,%3}, {%4,%5,%6,%7}, {%8,%9}, {%0,%1,%2,%3};"
        : "+f"(c[0]), "+f"(c[1]), "+f"(c[2]), "+f"(c[3])
        : "r"(a[0]), "r"(a[1]), "r"(a[2]), "r"(a[3]), "r"(b[0]), "r"(b[1]));
}

extern __shared__ __align__(16) char smem_dyn[];

__global__ __launch_bounds__(256, 2) void gemm_pipe_kernel(
    const float* __restrict__ feat, float* __restrict__ out) {

    char* smem = smem_dyn;
    const int tid  = threadIdx.x;
    const int wid  = tid >> 5;
    const int lane = tid & 31;
    const int wm   = wid >> 1;
    const int wn   = wid & 1;
    const int rowBase = blockIdx.x * 128;

    char* stg0 = smem + 512;
    char* stg1 = smem + 512 + STG_BYTES;

    if (tid < 128) ((float*)smem)[tid] = g_bsum[tid];

    float acc[2][8][4];
#pragma unroll
    for (int mt = 0; mt < 2; ++mt)
#pragma unroll
        for (int nt = 0; nt < 8; ++nt)
#pragma unroll
            for (int q = 0; q < 4; ++q) acc[mt][nt][q] = 0.f;

    const int lrow = lane >> 2;
    const int lkp  = lane & 3;

    float4 pf[4];

    // ---- prologue: stage phase 0 (self, kbase=0) into stg0 ----
    stage_w(stg0, 0, 0, tid);
    asm volatile("cp.async.commit_group;" ::: "memory");
    lda_self(feat, rowBase, 0, tid, pf);
    sts_self(stg0, tid, pf);

    for (int ph = 0; ph < 8; ++ph) {
        asm volatile("cp.async.wait_group 0;" ::: "memory");
        __syncthreads();

        char* cur = (ph & 1) ? stg1 : stg0;
        char* nxt = (ph & 1) ? stg0 : stg1;
        const bool have_next = (ph < 7);
        const bool next_self = (ph + 1) < 4;

        if (have_next) {
            int ns = (ph + 1) >> 2;
            int nk = ((ph + 1) & 3) * 32;
            stage_w(nxt, ns, nk, tid);
            if (!next_self) stage_a_neigh(nxt, rowBase, nk, tid);
            asm volatile("cp.async.commit_group;" ::: "memory");
            if (next_self) lda_self(feat, rowBase, nk, tid, pf);
        }

        // ---- compute phase ph from cur ----
#pragma unroll
        for (int k16 = 0; k16 < 2; ++k16) {
            const uint32_t kb = k16 * 32 + lkp * 4;

            uint32_t a_hi[2][4], a_lo[2][4];
#pragma unroll
            for (int mt = 0; mt < 2; ++mt) {
                uint32_t rb = (wm * 32 + mt * 16 + lrow) * AST2 + kb;
                a_hi[mt][0] = *(const uint32_t*)(cur + AHI + rb);
                a_hi[mt][1] = *(const uint32_t*)(cur + AHI + rb + 8 * AST2);
                a_hi[mt][2] = *(const uint32_t*)(cur + AHI + rb + 16);
                a_hi[mt][3] = *(const uint32_t*)(cur + AHI + rb + 8 * AST2 + 16);
                a_lo[mt][0] = *(const uint32_t*)(cur + ALO + rb);
                a_lo[mt][1] = *(const uint32_t*)(cur + ALO + rb + 8 * AST2);
                a_lo[mt][2] = *(const uint32_t*)(cur + ALO + rb + 16);
                a_lo[mt][3] = *(const uint32_t*)(cur + ALO + rb + 8 * AST2 + 16);
            }

#pragma unroll
            for (int nt = 0; nt < 8; ++nt) {
                uint32_t nb = (wn * 64 + nt * 8 + lrow) * AST2 + kb;
                uint32_t b_hi[2], b_lo[2];
                b_hi[0] = *(const uint32_t*)(cur + WHI + nb);
                b_hi[1] = *(const uint32_t*)(cur + WHI + nb + 16);
                b_lo[0] = *(const uint32_t*)(cur + WLO + nb);
                b_lo[1] = *(const uint32_t*)(cur + WLO + nb + 16);
#pragma unroll
                for (int mt = 0; mt < 2; ++mt) {
                    mma16816(acc[mt][nt], a_hi[mt], b_hi);
                    mma16816(acc[mt][nt], a_hi[mt], b_lo);
                    mma16816(acc[mt][nt], a_lo[mt], b_hi);
                }
            }
        }

        if (have_next && next_self) sts_self(nxt, tid, pf);
    }

    // ---- epilogue: bias + store ----
    const float* bias = (const float*)smem;
#pragma unroll
    for (int mt = 0; mt < 2; ++mt) {
        int r0 = rowBase + wm * 32 + mt * 16 + lrow;
#pragma unroll
        for (int nt = 0; nt < 8; ++nt) {
            int col = wn * 64 + nt * 8 + lkp * 2;
            float b0 = bias[col], b1 = bias[col + 1];
            float2 v0 = make_float2(acc[mt][nt][0] + b0, acc[mt][nt][1] + b1);
            float2 v1 = make_float2(acc[mt][nt][2] + b0, acc[mt][nt][3] + b1);
            *(float2*)(out + (size_t)r0 * D + col)       = v0;
            *(float2*)(out + (size_t)(r0 + 8) * D + col) = v1;
        }
    }
}

// ============================================================
// launch (2 kernels total)
// ============================================================
extern "C" void kernel_launch(void* const* d_in, const int* in_sizes, int n_in,
                              void* d_out, int out_size) {
    const float* feat   = (const float*)d_in[0];
    const float* Wself  = (const float*)d_in[1];
    const float* bself  = (const float*)d_in[2];
    const float* Wneigh = (const float*)d_in[3];
    const float* bneigh = (const float*)d_in[4];
    const int*   src    = (const int*)d_in[5];
    const int*   dst    = (const int*)d_in[6];

    int n_edges = in_sizes[5];
    int n_dst   = out_size / D;

    static bool attr_done = false;
    if (!attr_done) {
        cudaFuncSetAttribute(gemm_pipe_kernel,
                             cudaFuncAttributeMaxDynamicSharedMemorySize, S_TOTAL);
        attr_done = true;
    }

    // 1) aggregation (binary-search row bounds) + W prep trailing blocks
    {
        int threads = 256;
        int n_agg_blocks = (n_dst + 7) / 8;        // 8192
        aggregate_kernel<<<n_agg_blocks + 16, threads>>>(
            feat, src, dst, Wself, Wneigh, bself, bneigh,
            n_edges, n_dst, n_agg_blocks);
    }
    // 2) pipelined HMMA GEMM + bias (82 KB dynamic smem)
    {
        int blocks = n_dst / 128;   // 512
        gemm_pipe_kernel<<<blocks, 256, S_TOTAL>>>(feat, (float*)d_out);
    }
}

// round 16
// speedup vs baseline: 1.3736x; 1.3736x over previous
#include <cuda_runtime.h>
#include <cuda_bf16.h>
#include <cstdint>

#define D 128
#define MAX_DST 65536

// ---- scratch (__device__ globals per allocation rules) ----
__device__ int   g_off[MAX_DST + 1];
__device__ __align__(16) uint32_t g_hn_hi[(size_t)MAX_DST * 64];  // 16 MB: bf16x2 hi
__device__ __align__(16) uint32_t g_hn_lo[(size_t)MAX_DST * 64];  // 16 MB: bf16x2 lo
__device__ __align__(16) __nv_bfloat16 g_Wt_hi[2 * 128 * 128];    // [src][n][k] hi
__device__ __align__(16) __nv_bfloat16 g_Wt_lo[2 * 128 * 128];    // [src][n][k] lo
__device__ float g_bsum[128];

__device__ __forceinline__ uint32_t pack_bf16_hi(float a, float b, uint32_t& lo_out) {
    __nv_bfloat16 ha = __float2bfloat16(a);
    __nv_bfloat16 hb = __float2bfloat16(b);
    __nv_bfloat16 la = __float2bfloat16(a - __bfloat162float(ha));
    __nv_bfloat16 lb = __float2bfloat16(b - __bfloat162float(hb));
    lo_out = (uint32_t)__bfloat16_as_ushort(la) | ((uint32_t)__bfloat16_as_ushort(lb) << 16);
    return (uint32_t)__bfloat16_as_ushort(ha) | ((uint32_t)__bfloat16_as_ushort(hb) << 16);
}

// ============================================================
// Kernel 0: CSR offsets from SORTED dst (no atomics) + W prep fused
// ============================================================
__global__ void prep_kernel(const int* __restrict__ dst, int n_edges, int n_dst,
                            const float* __restrict__ Wself, const float* __restrict__ Wneigh,
                            const float* __restrict__ bself, const float* __restrict__ bneigh,
                            int offBlocks) {
    if ((int)blockIdx.x >= offBlocks) {
        int t = (blockIdx.x - offBlocks) * blockDim.x + threadIdx.x;
        for (int o = t; o < 2 * 128 * 128; o += 16 * 256) {
            int s = o >> 14, rem = o & 16383;
            int n = rem >> 7, k = rem & 127;
            const float* W = s ? Wneigh : Wself;
            float x = W[k * 128 + n];
            __nv_bfloat16 h = __float2bfloat16(x);
            g_Wt_hi[o] = h;
            g_Wt_lo[o] = __float2bfloat16(x - __bfloat162float(h));
        }
        if ((int)blockIdx.x == offBlocks && threadIdx.x < 128)
            g_bsum[threadIdx.x] = bself[threadIdx.x] + bneigh[threadIdx.x];
        return;
    }
    int e = blockIdx.x * blockDim.x + threadIdx.x;
    if (e > n_edges) return;
    if (e == 0) {
        int d1 = dst[0];
        for (int d = 0; d <= d1; ++d) g_off[d] = 0;
    } else if (e == n_edges) {
        int d0 = dst[n_edges - 1];
        for (int d = d0 + 1; d <= n_dst; ++d) g_off[d] = n_edges;
    } else {
        int d0 = dst[e - 1];
        int d1 = dst[e];
        for (int d = d0 + 1; d <= d1; ++d) g_off[d] = e;
    }
}

// ============================================================
// Kernel 1: segment-mean aggregation (R11 version — known best).
// One warp per dst row, 4-edge batches. Output bf16 hi/lo pairs.
// ============================================================
__global__ void aggregate_kernel(const float* __restrict__ feat,
                                 const int* __restrict__ src,
                                 int n_dst) {
    int warp = (int)((blockIdx.x * blockDim.x + threadIdx.x) >> 5);
    int lane = threadIdx.x & 31;
    if (warp >= n_dst) return;

    int lo = g_off[warp];
    int hi = g_off[warp + 1];

    const float4* __restrict__ fbase = (const float4*)feat;
    float ax = 0.f, ay = 0.f, az = 0.f, aw = 0.f;

    int e = lo;
    for (; e + 4 <= hi; e += 4) {
        int s0 = src[e + 0];
        int s1 = src[e + 1];
        int s2 = src[e + 2];
        int s3 = src[e + 3];
        float4 v0 = fbase[s0 * 32 + lane];
        float4 v1 = fbase[s1 * 32 + lane];
        float4 v2 = fbase[s2 * 32 + lane];
        float4 v3 = fbase[s3 * 32 + lane];
        ax += (v0.x + v1.x) + (v2.x + v3.x);
        ay += (v0.y + v1.y) + (v2.y + v3.y);
        az += (v0.z + v1.z) + (v2.z + v3.z);
        aw += (v0.w + v1.w) + (v2.w + v3.w);
    }
    for (; e < hi; ++e) {
        float4 v = fbase[src[e] * 32 + lane];
        ax += v.x; ay += v.y; az += v.z; aw += v.w;
    }

    float invd = 1.0f / fmaxf((float)(hi - lo), 1.0f);
    ax *= invd; ay *= invd; az *= invd; aw *= invd;

    uint32_t l0, l1;
    uint32_t h0 = pack_bf16_hi(ax, ay, l0);
    uint32_t h1 = pack_bf16_hi(az, aw, l1);
    size_t base = (size_t)warp * 64 + lane * 2;
    *(uint2*)&g_hn_hi[base] = make_uint2(h0, h1);
    *(uint2*)&g_hn_lo[base] = make_uint2(l0, l1);
}

// ============================================================
// Kernel 2: pipelined HMMA bf16-split GEMM with LDMATRIX fragment loads
//   out = [feat[:n_dst] | hn] @ [W_self ; W_neigh] + bias
// ============================================================
#define AST2 80                      // smem row stride in bytes
#define AHI 0
#define ALO 10240
#define WHI 20480
#define WLO 30720
#define STG_BYTES 40960
#define S_TOTAL (512 + 2 * STG_BYTES)   // 82432 B dynamic smem

__device__ __forceinline__ void cpa16(void* sdst, const void* gsrc) {
    uint32_t d = (uint32_t)__cvta_generic_to_shared(sdst);
    asm volatile("cp.async.cg.shared.global [%0], [%1], 16;" :: "r"(d), "l"(gsrc));
}
__device__ __forceinline__ void ldsm4(uint32_t* r, uint32_t saddr) {
    asm volatile("ldmatrix.sync.aligned.m8n8.x4.shared.b16 {%0,%1,%2,%3}, [%4];"
                 : "=r"(r[0]), "=r"(r[1]), "=r"(r[2]), "=r"(r[3]) : "r"(saddr));
}

__device__ __forceinline__ void stage_w(char* stg, int s, int kbase, int tid) {
#pragma unroll
    for (int i = 0; i < 2; ++i) {
        int c = tid + i * 256;
        int n = c >> 2, kc = c & 3;
        size_t go = ((size_t)(s * 128 + n)) * 128 + kbase + kc * 8;
        uint32_t off = n * AST2 + kc * 16;
        cpa16(stg + WHI + off, g_Wt_hi + go);
        cpa16(stg + WLO + off, g_Wt_lo + go);
    }
}
__device__ __forceinline__ void stage_a_neigh(char* stg, int rowBase, int kbase, int tid) {
#pragma unroll
    for (int i = 0; i < 2; ++i) {
        int c = tid + i * 256;
        int r = c >> 2, kc = c & 3;
        size_t gi = (size_t)(rowBase + r) * 64 + (kbase >> 1) + kc * 4;
        uint32_t off = r * AST2 + kc * 16;
        cpa16(stg + AHI + off, g_hn_hi + gi);
        cpa16(stg + ALO + off, g_hn_lo + gi);
    }
}
__device__ __forceinline__ void lda_self(const float* feat, int rowBase, int kbase,
                                         int tid, float4* pf) {
#pragma unroll
    for (int i = 0; i < 2; ++i) {
        int c = tid + i * 256;
        int r = c >> 2, kc = c & 3;
        const float4* p = (const float4*)(feat + (size_t)(rowBase + r) * D + kbase + kc * 8);
        pf[i * 2 + 0] = p[0];
        pf[i * 2 + 1] = p[1];
    }
}
__device__ __forceinline__ void sts_self(char* stg, int tid, const float4* pf) {
#pragma unroll
    for (int i = 0; i < 2; ++i) {
        int c = tid + i * 256;
        int r = c >> 2, kc = c & 3;
        float4 x0 = pf[i * 2 + 0], x1 = pf[i * 2 + 1];
        uint32_t h0, h1, h2, h3, l0, l1, l2, l3;
        h0 = pack_bf16_hi(x0.x, x0.y, l0);
        h1 = pack_bf16_hi(x0.z, x0.w, l1);
        h2 = pack_bf16_hi(x1.x, x1.y, l2);
        h3 = pack_bf16_hi(x1.z, x1.w, l3);
        uint32_t off = r * AST2 + kc * 16;
        *(uint4*)(stg + AHI + off) = make_uint4(h0, h1, h2, h3);
        *(uint4*)(stg + ALO + off) = make_uint4(l0, l1, l2, l3);
    }
}

__device__ __forceinline__ void mma16816(float* c, const uint32_t* a, const uint32_t* b) {
    asm volatile(
        "mma.sync.aligned.m16n8k16.row.col.f32.bf16.bf16.f32 "
        "{%0,%1,%2,%3}, {%4,%5,%6,%7}, {%8,%9}, {%0,%1,%2,%3};"
        : "+f"(c[0]), "+f"(c[1]), "+f"(c[2]), "+f"(c[3])
        : "r"(a[0]), "r"(a[1]), "r"(a[2]), "r"(a[3]), "r"(b[0]), "r"(b[1]));
}

extern __shared__ __align__(16) char smem_dyn[];

__global__ __launch_bounds__(256, 2) void gemm_pipe_kernel(
    const float* __restrict__ feat, float* __restrict__ out) {

    char* smem = smem_dyn;
    const int tid  = threadIdx.x;
    const int wid  = tid >> 5;
    const int lane = tid & 31;
    const int wm   = wid >> 1;
    const int wn   = wid & 1;
    const int rowBase = blockIdx.x * 128;

    char* stg0 = smem + 512;
    char* stg1 = smem + 512 + STG_BYTES;
    const uint32_t s0u = (uint32_t)__cvta_generic_to_shared(stg0);
    const uint32_t s1u = (uint32_t)__cvta_generic_to_shared(stg1);

    if (tid < 128) ((float*)smem)[tid] = g_bsum[tid];

    float acc[2][8][4];
#pragma unroll
    for (int mt = 0; mt < 2; ++mt)
#pragma unroll
        for (int nt = 0; nt < 8; ++nt)
#pragma unroll
            for (int q = 0; q < 4; ++q) acc[mt][nt][q] = 0.f;

    // ldmatrix lane addressing (fragment orders verified vs mma layouts)
    const uint32_t a_row_off = (uint32_t)(wm * 32 + (lane & 15)) * AST2 + ((lane >> 4) << 4);
    const uint32_t b_row_off = (uint32_t)(wn * 64 + ((lane >> 4) << 3) + (lane & 7)) * AST2
                             + (((lane >> 3) & 1) << 4);

    float4 pf[4];

    stage_w(stg0, 0, 0, tid);
    asm volatile("cp.async.commit_group;" ::: "memory");
    lda_self(feat, rowBase, 0, tid, pf);
    sts_self(stg0, tid, pf);

    for (int ph = 0; ph < 8; ++ph) {
        asm volatile("cp.async.wait_group 0;" ::: "memory");
        __syncthreads();

        char* nxt = (ph & 1) ? stg0 : stg1;
        const uint32_t cu = (ph & 1) ? s1u : s0u;
        const bool have_next = (ph < 7);
        const bool next_self = (ph + 1) < 4;

        if (have_next) {
            int ns = (ph + 1) >> 2;
            int nk = ((ph + 1) & 3) * 32;
            stage_w(nxt, ns, nk, tid);
            if (!next_self) stage_a_neigh(nxt, rowBase, nk, tid);
            asm volatile("cp.async.commit_group;" ::: "memory");
            if (next_self) lda_self(feat, rowBase, nk, tid, pf);
        }

        // ---- compute phase ph (ldmatrix fragments) ----
#pragma unroll
        for (int k16 = 0; k16 < 2; ++k16) {
            const uint32_t kb16 = k16 * 32;

            uint32_t a_hi[2][4], a_lo[2][4];
#pragma unroll
            for (int mt = 0; mt < 2; ++mt) {
                uint32_t ar = cu + a_row_off + (uint32_t)(mt * 16) * AST2 + kb16;
                ldsm4(a_hi[mt], ar + AHI);
                ldsm4(a_lo[mt], ar + ALO);
            }

#pragma unroll
            for (int j = 0; j < 4; ++j) {          // nt pairs (2j, 2j+1)
                uint32_t br = cu + b_row_off + (uint32_t)(j * 16) * AST2 + kb16;
                uint32_t bh[4], bl[4];
                ldsm4(bh, br + WHI);
                ldsm4(bl, br + WLO);
#pragma unroll
                for (int h = 0; h < 2; ++h) {      // nt = 2j + h
                    int nt = 2 * j + h;
#pragma unroll
                    for (int mt = 0; mt < 2; ++mt) {
                        mma16816(acc[mt][nt], a_hi[mt], bh + 2 * h);
                        mma16816(acc[mt][nt], a_hi[mt], bl + 2 * h);
                        mma16816(acc[mt][nt], a_lo[mt], bh + 2 * h);
                    }
                }
            }
        }

        if (have_next && next_self) sts_self(nxt, tid, pf);
    }

    // ---- epilogue: bias + store ----
    const int lrow = lane >> 2;
    const int lkp  = lane & 3;
    const float* bias = (const float*)smem;
#pragma unroll
    for (int mt = 0; mt < 2; ++mt) {
        int r0 = rowBase + wm * 32 + mt * 16 + lrow;
#pragma unroll
        for (int nt = 0; nt < 8; ++nt) {
            int col = wn * 64 + nt * 8 + lkp * 2;
            float b0 = bias[col], b1 = bias[col + 1];
            float2 v0 = make_float2(acc[mt][nt][0] + b0, acc[mt][nt][1] + b1);
            float2 v1 = make_float2(acc[mt][nt][2] + b0, acc[mt][nt][3] + b1);
            *(float2*)(out + (size_t)r0 * D + col)       = v0;
            *(float2*)(out + (size_t)(r0 + 8) * D + col) = v1;
        }
    }
}

// ============================================================
// launch
// ============================================================
extern "C" void kernel_launch(void* const* d_in, const int* in_sizes, int n_in,
                              void* d_out, int out_size) {
    const float* feat   = (const float*)d_in[0];
    const float* Wself  = (const float*)d_in[1];
    const float* bself  = (const float*)d_in[2];
    const float* Wneigh = (const float*)d_in[3];
    const float* bneigh = (const float*)d_in[4];
    const int*   src    = (const int*)d_in[5];
    const int*   dst    = (const int*)d_in[6];

    int n_edges = in_sizes[5];
    int n_dst   = out_size / D;

    static bool attr_done = false;
    if (!attr_done) {
        cudaFuncSetAttribute(gemm_pipe_kernel,
                             cudaFuncAttributeMaxDynamicSharedMemorySize, S_TOTAL);
        attr_done = true;
    }

    // 0) CSR offsets + W bf16 split/transpose + bias sum (fused)
    {
        int threads = 256;
        int offBlocks = (n_edges + 1 + threads - 1) / threads;
        prep_kernel<<<offBlocks + 16, threads>>>(dst, n_edges, n_dst,
                                                 Wself, Wneigh, bself, bneigh, offBlocks);
    }
    // 1) segment-mean aggregation -> bf16 hi/lo
    {
        int threads = 256;
        int blocks = (n_dst + 7) / 8;
        aggregate_kernel<<<blocks, threads>>>(feat, src, n_dst);
    }
    // 2) pipelined HMMA GEMM (ldmatrix fragments) + bias
    {
        int blocks = n_dst / 128;   // 512
        gemm_pipe_kernel<<<blocks, 256, S_TOTAL>>>(feat, (float*)d_out);
    }
}